// round 2
// baseline (speedup 1.0000x reference)
#include <cuda_runtime.h>
#include <cuda_bf16.h>

#define VOCAB 32000
#define NROWS 4096
#define N4    (VOCAB / 4)   // 8000 float4 per row

// Per-row scratch (allocation-free rule: __device__ globals)
__device__ float g_w[NROWS];   // weighted value at target column (0 if invalid)
__device__ float g_v[NROWS];   // 1.0 if row valid (target != -1) else 0.0

// Merge two (max, scaled-sum) softmax partials
__device__ __forceinline__ void merge_ms(float& m, float& s, float om, float os) {
    float nm = fmaxf(m, om);
    s = s * __expf(m - nm) + os * __expf(om - nm);
    m = nm;
}

__global__ void __launch_bounds__(256) gwloss_row_kernel(
    const float* __restrict__ x, const int* __restrict__ tgt)
{
    const int row = blockIdx.x;
    const float4* __restrict__ rp =
        reinterpret_cast<const float4*>(x + (size_t)row * VOCAB);

    // One-pass online softmax statistics (per-thread)
    float m = -3.0e38f;
    float s = 0.0f;

    for (int i = threadIdx.x; i < N4; i += 256) {
        float4 v = rp[i];
        float lm = fmaxf(fmaxf(v.x, v.y), fmaxf(v.z, v.w));
        if (lm > m) { s *= __expf(m - lm); m = lm; }
        s += __expf(v.x - m);
        s += __expf(v.y - m);
        s += __expf(v.z - m);
        s += __expf(v.w - m);
    }

    // Warp-level merge
    #pragma unroll
    for (int off = 16; off > 0; off >>= 1) {
        float om = __shfl_xor_sync(0xFFFFFFFFu, m, off);
        float os = __shfl_xor_sync(0xFFFFFFFFu, s, off);
        merge_ms(m, s, om, os);
    }

    // Cross-warp merge via shared memory (8 warps)
    __shared__ float sm[8];
    __shared__ float ss[8];
    const int wid = threadIdx.x >> 5;
    const int lid = threadIdx.x & 31;
    if (lid == 0) { sm[wid] = m; ss[wid] = s; }
    __syncthreads();

    if (wid == 0) {
        // lanes 0..7 hold partials, merge down with shuffles
        m = (lid < 8) ? sm[lid] : -3.0e38f;
        s = (lid < 8) ? ss[lid] : 0.0f;
        #pragma unroll
        for (int off = 4; off > 0; off >>= 1) {
            float om = __shfl_xor_sync(0xFFFFFFFFu, m, off);
            float os = __shfl_xor_sync(0xFFFFFFFFu, s, off);
            merge_ms(m, s, om, os);
        }

        if (lid == 0) {
            int t = tgt[row];
            float w = 0.0f, val = 0.0f;
            if (t >= 0 && t < VOCAB) {
                float xt    = x[(size_t)row * VOCAB + (size_t)t];
                float logpt = xt - m - logf(s);     // exact logf in epilogue
                float pt    = expf(logpt);
                // mean = 0.5, variance = 0.1*e  ->  2*variance^2 = 0.02*e^2
                const float inv_2var2 = 1.0f / 0.14778112197861f;
                float d = pt - 0.5f;
                float g = expf(-(d * d) * inv_2var2);
                w   = (g - 0.1f * pt) * logpt;
                val = 1.0f;
            }
            g_w[row] = w;
            g_v[row] = val;
        }
    }
}

__global__ void __launch_bounds__(256) gwloss_finalize_kernel(float* __restrict__ out)
{
    double w = 0.0, v = 0.0;
    for (int i = threadIdx.x; i < NROWS; i += 256) {
        w += (double)g_w[i];
        v += (double)g_v[i];
    }
    __shared__ double swm[256];
    __shared__ double svm[256];
    swm[threadIdx.x] = w;
    svm[threadIdx.x] = v;
    __syncthreads();
    for (int off = 128; off > 0; off >>= 1) {
        if (threadIdx.x < off) {
            swm[threadIdx.x] += swm[threadIdx.x + off];
            svm[threadIdx.x] += svm[threadIdx.x + off];
        }
        __syncthreads();
    }
    if (threadIdx.x == 0) {
        out[0] = (float)(-swm[0] / svm[0]);
    }
}

extern "C" void kernel_launch(void* const* d_in, const int* in_sizes, int n_in,
                              void* d_out, int out_size) {
    const float* x   = (const float*)d_in[0];
    const int*   tgt = (const int*)d_in[1];
    float*       out = (float*)d_out;

    gwloss_row_kernel<<<NROWS, 256>>>(x, tgt);
    gwloss_finalize_kernel<<<1, 256>>>(out);
}